// round 4
// baseline (speedup 1.0000x reference)
#include <cuda_runtime.h>
#include <cstdint>

// MeanAggregator: out[b, :] = (1/S) * sum_{s<S} features[neigh_idx[b,s], :]
// B=50000, S=10, N=1e6, D=128 (fp32), neigh_idx int32.
// R4: half-warp per node; each of 16 lanes owns 32B (8 floats) of the row.
// 256-bit gathers with L2::evict_last (feature table is the only reusable
// data), 256-bit stores with L2::evict_first. Gathers in 2 waves of 5 to
// bound register pressure.

#define D_DIM 128

struct F8 { float f[8]; };

__device__ __forceinline__ F8 ldg_v8_evict_last(const float* p) {
    F8 v;
    asm("ld.global.nc.L2::evict_last.v8.b32 {%0,%1,%2,%3,%4,%5,%6,%7}, [%8];"
        : "=f"(v.f[0]), "=f"(v.f[1]), "=f"(v.f[2]), "=f"(v.f[3]),
          "=f"(v.f[4]), "=f"(v.f[5]), "=f"(v.f[6]), "=f"(v.f[7])
        : "l"(p));
    return v;
}

__device__ __forceinline__ void stg_v8_evict_first(float* p, const F8& v) {
    asm volatile("st.global.L2::evict_first.v8.b32 [%0], {%1,%2,%3,%4,%5,%6,%7,%8};"
                 :: "l"(p),
                    "f"(v.f[0]), "f"(v.f[1]), "f"(v.f[2]), "f"(v.f[3]),
                    "f"(v.f[4]), "f"(v.f[5]), "f"(v.f[6]), "f"(v.f[7])
                 : "memory");
}

template<int S>
__global__ __launch_bounds__(256)
void mean_agg_kernel(const int* __restrict__ neigh_idx,
                     const float* __restrict__ features,
                     float* __restrict__ out,
                     int B, float inv_s)
{
    int gid  = blockIdx.x * blockDim.x + threadIdx.x;
    int node = gid >> 4;        // 16 lanes per node
    int lane = gid & 15;        // owns floats [lane*8, lane*8+8)
    if (node >= B) return;

    const int* __restrict__ idx_row = neigh_idx + (long long)node * S;

    int rows[S];
#pragma unroll
    for (int s = 0; s < S; s++) rows[s] = __ldg(idx_row + s);

    constexpr int W1 = S - S / 2;   // first wave size
    float acc[8];
#pragma unroll
    for (int i = 0; i < 8; i++) acc[i] = 0.f;

    // Wave 1
    {
        F8 v[W1];
#pragma unroll
        for (int s = 0; s < W1; s++)
            v[s] = ldg_v8_evict_last(features + (long long)rows[s] * D_DIM + lane * 8);
#pragma unroll
        for (int s = 0; s < W1; s++)
#pragma unroll
            for (int i = 0; i < 8; i++) acc[i] += v[s].f[i];
    }
    // Wave 2
    {
        constexpr int W2 = S / 2;
        F8 v[W2 > 0 ? W2 : 1];
#pragma unroll
        for (int s = 0; s < W2; s++)
            v[s] = ldg_v8_evict_last(features + (long long)rows[W1 + s] * D_DIM + lane * 8);
#pragma unroll
        for (int s = 0; s < W2; s++)
#pragma unroll
            for (int i = 0; i < 8; i++) acc[i] += v[s].f[i];
    }

    F8 r;
#pragma unroll
    for (int i = 0; i < 8; i++) r.f[i] = acc[i] * inv_s;

    stg_v8_evict_first(out + (long long)node * D_DIM + lane * 8, r);
}

// Generic fallback (S not known at compile time).
__global__ __launch_bounds__(256)
void mean_agg_kernel_dyn(const int* __restrict__ neigh_idx,
                         const float* __restrict__ features,
                         float* __restrict__ out,
                         int B, int S, float inv_s)
{
    int gid  = blockIdx.x * blockDim.x + threadIdx.x;
    int node = gid >> 5;
    int lane = gid & 31;
    if (node >= B) return;

    const int* __restrict__ idx_row = neigh_idx + (long long)node * S;
    float4 acc = make_float4(0.f, 0.f, 0.f, 0.f);
    for (int s = 0; s < S; s++) {
        int r = idx_row[s];
        float4 vv = __ldg(reinterpret_cast<const float4*>(
            features + (long long)r * D_DIM) + lane);
        acc.x += vv.x; acc.y += vv.y; acc.z += vv.z; acc.w += vv.w;
    }
    acc.x *= inv_s; acc.y *= inv_s; acc.z *= inv_s; acc.w *= inv_s;
    reinterpret_cast<float4*>(out + (long long)node * D_DIM)[lane] = acc;
}

extern "C" void kernel_launch(void* const* d_in, const int* in_sizes, int n_in,
                              void* d_out, int out_size)
{
    const int*   neigh_idx = (const int*)d_in[0];   // [B, S] int32
    const float* features  = (const float*)d_in[1]; // [N, D] fp32

    int B = out_size / D_DIM;
    int S = in_sizes[0] / B;
    float inv_s = 1.0f / (float)S;
    float* out = (float*)d_out;

    if (S == 10) {
        long long threads = (long long)B * 16;
        int grid = (int)((threads + 255) / 256);
        mean_agg_kernel<10><<<grid, 256>>>(neigh_idx, features, out, B, inv_s);
    } else {
        long long threads = (long long)B * 32;
        int grid = (int)((threads + 255) / 256);
        mean_agg_kernel_dyn<<<grid, 256>>>(neigh_idx, features, out, B, S, inv_s);
    }
}

// round 5
// speedup vs baseline: 1.0548x; 1.0548x over previous
#include <cuda_runtime.h>
#include <cstdint>

// MeanAggregator: out[b, :] = (1/S) * sum_{s<S} features[neigh_idx[b,s], :]
// B=50000, S=10, N=1e6, D=128 (fp32), neigh_idx int32.
// R5: back to warp-per-node float4 gather (R2 structure), but WITHOUT the
// __launch_bounds__ min-blocks clamp that forced 32 regs and silently
// serialized the 10 gathers. Let ptxas keep all 10 LDG.128 in flight.

#define D_DIM 128

template<int S>
__global__ __launch_bounds__(256)
void mean_agg_kernel(const int* __restrict__ neigh_idx,
                     const float* __restrict__ features,
                     float* __restrict__ out,
                     int B, float inv_s)
{
    int warp = (blockIdx.x * blockDim.x + threadIdx.x) >> 5;
    int lane = threadIdx.x & 31;
    if (warp >= B) return;

    const int* __restrict__ idx_row = neigh_idx + (long long)warp * S;

    // All lanes load the same S indices (L1 broadcast).
    int rows[S];
#pragma unroll
    for (int s = 0; s < S; s++) rows[s] = __ldg(idx_row + s);

    // Front-batch all S gathers: independent LDG.128s, max MLP.
    float4 v[S];
#pragma unroll
    for (int s = 0; s < S; s++) {
        const float4* p = reinterpret_cast<const float4*>(
            features + (long long)rows[s] * D_DIM) + lane;
        v[s] = __ldg(p);
    }

    float4 acc = make_float4(0.f, 0.f, 0.f, 0.f);
#pragma unroll
    for (int s = 0; s < S; s++) {
        acc.x += v[s].x; acc.y += v[s].y; acc.z += v[s].z; acc.w += v[s].w;
    }
    acc.x *= inv_s; acc.y *= inv_s; acc.z *= inv_s; acc.w *= inv_s;

    float4* o = reinterpret_cast<float4*>(out + (long long)warp * D_DIM) + lane;
    *o = acc;
}

// Generic fallback (S not known at compile time).
__global__ __launch_bounds__(256)
void mean_agg_kernel_dyn(const int* __restrict__ neigh_idx,
                         const float* __restrict__ features,
                         float* __restrict__ out,
                         int B, int S, float inv_s)
{
    int warp = (blockIdx.x * blockDim.x + threadIdx.x) >> 5;
    int lane = threadIdx.x & 31;
    if (warp >= B) return;

    const int* __restrict__ idx_row = neigh_idx + (long long)warp * S;
    float4 acc = make_float4(0.f, 0.f, 0.f, 0.f);
    for (int s = 0; s < S; s++) {
        int r = idx_row[s];
        float4 vv = __ldg(reinterpret_cast<const float4*>(
            features + (long long)r * D_DIM) + lane);
        acc.x += vv.x; acc.y += vv.y; acc.z += vv.z; acc.w += vv.w;
    }
    acc.x *= inv_s; acc.y *= inv_s; acc.z *= inv_s; acc.w *= inv_s;
    reinterpret_cast<float4*>(out + (long long)warp * D_DIM)[lane] = acc;
}

extern "C" void kernel_launch(void* const* d_in, const int* in_sizes, int n_in,
                              void* d_out, int out_size)
{
    const int*   neigh_idx = (const int*)d_in[0];   // [B, S] int32
    const float* features  = (const float*)d_in[1]; // [N, D] fp32

    int B = out_size / D_DIM;
    int S = in_sizes[0] / B;
    float inv_s = 1.0f / (float)S;
    float* out = (float*)d_out;

    int warps_per_block = 256 / 32;
    int grid = (B + warps_per_block - 1) / warps_per_block;

    if (S == 10) {
        mean_agg_kernel<10><<<grid, 256>>>(neigh_idx, features, out, B, inv_s);
    } else {
        mean_agg_kernel_dyn<<<grid, 256>>>(neigh_idx, features, out, B, S, inv_s);
    }
}